// round 1
// baseline (speedup 1.0000x reference)
#include <cuda_runtime.h>

#define H 4096
#define W 4096
#define OH 4090
#define OW 4090

#define BX_TILE 128
#define BY_TILE 32
#define SH_ROWS 38      // BY_TILE + 6
#define SH_PITCH 136    // BX_TILE + 6 rounded up to mult of 8; 544B row stride (16B-aligned)
#define LOAD_C4 34      // float4 columns loaded per tile row (136 floats)

__device__ __forceinline__ unsigned long long pack2(float lo, float hi) {
    unsigned long long r;
    asm("mov.b64 %0, {%1, %2};" : "=l"(r) : "f"(lo), "f"(hi));
    return r;
}
__device__ __forceinline__ void unpack2(unsigned long long v, float &lo, float &hi) {
    asm("mov.b64 {%0, %1}, %2;" : "=f"(lo), "=f"(hi) : "l"(v));
}
__device__ __forceinline__ void ffma2(unsigned long long &d, unsigned long long a, unsigned long long b) {
    asm("fma.rn.f32x2 %0, %1, %2, %3;" : "=l"(d) : "l"(a), "l"(b), "l"(d));
}

__global__ __launch_bounds__(256)
void conv7x7_kernel(const float* __restrict__ X,
                    const float* __restrict__ Wt,
                    const float* __restrict__ Bs,
                    float* __restrict__ out) {
    __shared__ float tile[SH_ROWS][SH_PITCH];
    __shared__ float2 w2[49];

    const int tid = threadIdx.x;
    const int bx = blockIdx.x * BX_TILE;
    const int by = blockIdx.y * BY_TILE;

    // Duplicate weights into (w, w) f32x2 pairs for packed FMA.
    if (tid < 49) {
        float w = Wt[tid];
        w2[tid] = make_float2(w, w);
    }

    // Cooperative tile load: 38 rows x 34 float4. Clamp row/col bases so all
    // loads stay in-bounds; clamped (wrong) halo values only feed outputs that
    // are predicated off in the epilogue.
    for (int idx = tid; idx < SH_ROWS * LOAD_C4; idx += 256) {
        int r  = idx / LOAD_C4;
        int c4 = idx - r * LOAD_C4;
        int gy = by + r;        if (gy > H - 1) gy = H - 1;
        int gx = bx + c4 * 4;   if (gx > W - 4) gx = W - 4;
        float4 v = *reinterpret_cast<const float4*>(X + (size_t)gy * W + gx);
        *reinterpret_cast<float4*>(&tile[r][c4 * 4]) = v;
    }
    __syncthreads();

    const int tx = tid & 31;
    const int ty = tid >> 5;
    const int ox0 = tx * 4;   // output col within tile
    const int oy0 = ty * 4;   // output row within tile

    unsigned long long acc[4][2];
#pragma unroll
    for (int i = 0; i < 4; i++) { acc[i][0] = 0ull; acc[i][1] = 0ull; }

    // Stream 10 input rows; each contributes to up to 4 output rows.
#pragma unroll
    for (int il = 0; il < 10; il++) {
        const float* rp = &tile[oy0 + il][ox0];
        float4 a = *reinterpret_cast<const float4*>(rp);
        float4 b = *reinterpret_cast<const float4*>(rp + 4);
        float4 c = *reinterpret_cast<const float4*>(rp + 8);
        float r[12] = {a.x, a.y, a.z, a.w, b.x, b.y, b.z, b.w, c.x, c.y, c.z, c.w};

        unsigned long long p[9];
#pragma unroll
        for (int j = 0; j < 9; j++) p[j] = pack2(r[j], r[j + 1]);

#pragma unroll
        for (int oy = 0; oy < 4; oy++) {
            const int ky = il - oy;
            if (ky < 0 || ky > 6) continue;   // compile-time pruned
#pragma unroll
            for (int kx = 0; kx < 7; kx++) {
                unsigned long long wp =
                    *reinterpret_cast<const unsigned long long*>(&w2[ky * 7 + kx]);
                ffma2(acc[oy][0], p[kx],     wp);  // outputs ox0+0, ox0+1
                ffma2(acc[oy][1], p[kx + 2], wp);  // outputs ox0+2, ox0+3
            }
        }
    }

    const float bias = Bs[0];

#pragma unroll
    for (int oy = 0; oy < 4; oy++) {
        const int orow = by + oy0 + oy;
        if (orow >= OH) continue;
        const int ocol = bx + ox0;
        float o0, o1, o2, o3;
        unpack2(acc[oy][0], o0, o1);
        unpack2(acc[oy][1], o2, o3);
        o0 += bias; o1 += bias; o2 += bias; o3 += bias;
        const size_t base = (size_t)orow * OW + ocol;

        if (ocol + 3 < OW) {
            // base mod 4 == 2*orow mod 4 (OW=4090 ≡ 2 mod 4, ocol ≡ 0 mod 4):
            // even rows are 16B-aligned, odd rows are 8B-aligned.
            if ((orow & 1) == 0) {
                *reinterpret_cast<float4*>(out + base) = make_float4(o0, o1, o2, o3);
            } else {
                *reinterpret_cast<float2*>(out + base)     = make_float2(o0, o1);
                *reinterpret_cast<float2*>(out + base + 2) = make_float2(o2, o3);
            }
        } else {
            float ov[4] = {o0, o1, o2, o3};
#pragma unroll
            for (int c = 0; c < 4; c++)
                if (ocol + c < OW) out[base + c] = ov[c];
        }
    }
}

extern "C" void kernel_launch(void* const* d_in, const int* in_sizes, int n_in,
                              void* d_out, int out_size) {
    const float* X  = (const float*)d_in[0];
    const float* Wt = (const float*)d_in[1];
    const float* Bs = (const float*)d_in[2];
    float* out = (float*)d_out;
    dim3 grid((OW + BX_TILE - 1) / BX_TILE, (OH + BY_TILE - 1) / BY_TILE);
    conv7x7_kernel<<<grid, 256>>>(X, Wt, Bs, out);
}